// round 6
// baseline (speedup 1.0000x reference)
#include <cuda_runtime.h>
#include <cuda_fp16.h>
#include <cstdint>
#include <cstddef>

// ===================== problem sizes =====================
static constexpr int MM   = 8192;   // state_len (rows)
static constexpr int NN   = 8192;   // seq_len   (cols, softmax axis)
static constexpr int KK   = 1024;   // hidden
static constexpr int KTOT = 3072;   // 3*KK : [hi*hi | lo*hi | hi*lo]

// ===================== GEMM config =====================
// 128x128 CTA tile, 3-stage pipeline, 96KB smem -> 2 CTAs per SM.
// K-chunks processed in rotated order: corrections (16..47) first with f16
// accumulation (2x tensor rate), then hi*hi (0..15) with f32 accumulation.
static constexpr int BM = 128, BN = 128, BK = 64;   // BK fp16 = 128B row
static constexpr int STAGES  = 3;
static constexpr int NCHUNK  = KTOT / BK;           // 48
static constexpr int NCORR   = 32;                  // correction chunks (f16 acc)
static constexpr int TILES_M = MM / BM;             // 64
static constexpr int TILES_N = NN / BN;             // 64
static constexpr int A_STAGE = BM * BK * 2;         // 16384
static constexpr int B_STAGE = BN * BK * 2;         // 16384
static constexpr int STAGE_BYTES = A_STAGE + B_STAGE;          // 32768
static constexpr int GEMM_SMEM   = STAGES * STAGE_BYTES;       // 98304

// ===================== scratch (allocation-free) =====================
__device__ __half g_Ah[(size_t)MM * KTOT];   // 48 MB
__device__ __half g_Bh[(size_t)NN * KTOT];   // 48 MB

// ===================== PTX helpers (base sm_100-safe) =====================
__device__ __forceinline__ uint32_t smem_to_u32(const void* p) {
    uint32_t a;
    asm("{ .reg .u64 t; cvta.to.shared.u64 t, %1; cvt.u32.u64 %0, t; }"
        : "=r"(a) : "l"(p));
    return a;
}

#define CP_ASYNC_16(dst, src) \
    asm volatile("cp.async.cg.shared.global [%0], [%1], 16;" \
                 :: "r"(dst), "l"(src) : "memory")
#define CP_COMMIT() \
    asm volatile("cp.async.commit_group;" ::: "memory")
#define CP_WAIT(n) \
    asm volatile("cp.async.wait_group %0;" :: "n"(n) : "memory")

#define LDSM_X4(r0, r1, r2, r3, addr) \
    asm volatile("ldmatrix.sync.aligned.m8n8.x4.shared.b16 {%0,%1,%2,%3}, [%4];" \
                 : "=r"(r0), "=r"(r1), "=r"(r2), "=r"(r3) : "r"(addr))

// fp32-accumulate MMA (rt ~8)
#define MMA16816(d, a, b) \
    asm volatile("mma.sync.aligned.m16n8k16.row.col.f32.f16.f16.f32 " \
                 "{%0,%1,%2,%3}, {%4,%5,%6,%7}, {%8,%9}, {%0,%1,%2,%3};" \
                 : "+f"((d)[0]), "+f"((d)[1]), "+f"((d)[2]), "+f"((d)[3]) \
                 : "r"((a)[0]), "r"((a)[1]), "r"((a)[2]), "r"((a)[3]), \
                   "r"((b)[0]), "r"((b)[1]))

// fp16-accumulate MMA (rt ~4, 2x rate) — used for the small correction terms
#define MMA16816_F16(d, a, b) \
    asm volatile("mma.sync.aligned.m16n8k16.row.col.f16.f16.f16.f16 " \
                 "{%0,%1}, {%2,%3,%4,%5}, {%6,%7}, {%0,%1};" \
                 : "+r"((d)[0]), "+r"((d)[1]) \
                 : "r"((a)[0]), "r"((a)[1]), "r"((a)[2]), "r"((a)[3]), \
                   "r"((b)[0]), "r"((b)[1]))

// SW128-style XOR swizzle: 128B rows, 8 x 16B chunks; chunk' = chunk ^ (row & 7)
__device__ __forceinline__ uint32_t sw_off(int row, int chunk) {
    return (uint32_t)(row * 128 + (((chunk) ^ (row & 7)) << 4));
}

// chunk visit order: 16..47 (corrections) then 0..15 (hi*hi)
__device__ __forceinline__ int kc_of(int i) {
    return (i < NCORR) ? (16 + i) : (i - NCORR);
}

// ===================== kernel 1: fp32 -> fp16 3-way split =====================
__device__ __forceinline__ void split2(float x, __half& h, __half& l) {
    h = __float2half_rn(x);
    l = __float2half_rn(x - __half2float(h));
}
__device__ __forceinline__ void st4h(__half* p, __half a, __half b, __half c, __half d) {
    __half2 lo = __halves2half2(a, b);
    __half2 hi = __halves2half2(c, d);
    uint2 u;
    u.x = *reinterpret_cast<uint32_t*>(&lo);
    u.y = *reinterpret_cast<uint32_t*>(&hi);
    *reinterpret_cast<uint2*>(p) = u;
}

__global__ void __launch_bounds__(256) convert_kernel(
    const float* __restrict__ A, const float* __restrict__ B,
    __half* __restrict__ Ah, __half* __restrict__ Bh)
{
    int idx = blockIdx.x * 256 + threadIdx.x;   // float4 index
    int i  = idx >> 8;                          // row (KK/4 = 256 float4 per row)
    int k4 = idx & 255;
    size_t base = (size_t)i * KTOT + (size_t)k4 * 4;

    float4 a = reinterpret_cast<const float4*>(A)[idx];
    float4 b = reinterpret_cast<const float4*>(B)[idx];

    __half ah0, al0, ah1, al1, ah2, al2, ah3, al3;
    split2(a.x, ah0, al0); split2(a.y, ah1, al1);
    split2(a.z, ah2, al2); split2(a.w, ah3, al3);
    st4h(Ah + base,          ah0, ah1, ah2, ah3);   // hi
    st4h(Ah + base + KK,     al0, al1, al2, al3);   // lo
    st4h(Ah + base + 2 * KK, ah0, ah1, ah2, ah3);   // hi

    __half bh0, bl0, bh1, bl1, bh2, bl2, bh3, bl3;
    split2(b.x, bh0, bl0); split2(b.y, bh1, bl1);
    split2(b.z, bh2, bl2); split2(b.w, bh3, bl3);
    st4h(Bh + base,          bh0, bh1, bh2, bh3);   // hi
    st4h(Bh + base + KK,     bh0, bh1, bh2, bh3);   // hi
    st4h(Bh + base + 2 * KK, bl0, bl1, bl2, bl3);   // lo
}

// ===================== kernel 2: mma.sync fp16 GEMM =====================
// out[m, n] = sum_k A'[m,k] * B'[n,k]   (fp32)
// CTA tile 128x128, 8 warps (2M x 4N), warp tile 64x32. 2 CTAs/SM.
__global__ void __launch_bounds__(256, 2)
gemm_kernel(const __half* __restrict__ Ah, const __half* __restrict__ Bh,
            float* __restrict__ out)
{
    extern __shared__ __align__(1024) char smem[];
    const uint32_t sb = smem_to_u32(smem);
    const int tid = threadIdx.x;
    const int wid = tid >> 5;
    const int lid = tid & 31;

    // supertile swizzle for L2 reuse: 8x8 groups
    constexpr int PER_G = 64;
    constexpr int GROUPS_N = TILES_N / 8;   // 8
    int id = blockIdx.x;
    int g = id / PER_G, r = id % PER_G;
    int tm = (g / GROUPS_N) * 8 + r / 8;
    int tn = (g % GROUPS_N) * 8 + r % 8;
    const int m0 = tm * BM, n0 = tn * BN;

    // warp layout: 2 (M) x 4 (N); warp tile 64 x 32
    const int wm = wid & 1;        // 0..1
    const int wn = wid >> 1;       // 0..3

    // cp.async assignment: 16B chunks; row step 32 across iterations
    const int lr = tid >> 3;       // base row (0..31)
    const int lc = tid & 7;        // chunk 0..7

    const __half* gA = Ah + (size_t)(m0 + lr) * KTOT + lc * 8;
    const __half* gB = Bh + (size_t)(n0 + lr) * KTOT + lc * 8;

    // ---- load one stage of A+B via cp.async (4 A rows + 4 B rows per thread) ----
    auto load_stage = [&](int s, int kc) {
        uint32_t a_s = sb + s * STAGE_BYTES;
        uint32_t b_s = a_s + A_STAGE;
        const __half* ga = gA + (size_t)kc * BK;
        const __half* gb = gB + (size_t)kc * BK;
        #pragma unroll
        for (int i = 0; i < 4; i++) {
            CP_ASYNC_16(a_s + sw_off(lr + i * 32, lc), ga + (size_t)i * 32 * KTOT);
            CP_ASYNC_16(b_s + sw_off(lr + i * 32, lc), gb + (size_t)i * 32 * KTOT);
        }
    };

    // prologue: fill STAGES-1 stages (chunk order starts at 16)
    #pragma unroll
    for (int s = 0; s < STAGES - 1; s++) {
        load_stage(s, kc_of(s));
        CP_COMMIT();
    }

    // ldmatrix lane addressing (within a stage)
    const int a_row_l = wm * 64 + (lid & 15);
    const int a_chk_l = (lid >> 4);
    const int b_row_l = wn * 32 + (lid & 7) + ((lid >> 4) & 1) * 8;
    const int b_chk_l = (lid >> 3) & 1;

    auto load_frags = [&](uint32_t a_s, uint32_t b_s, int kk,
                          uint32_t af[][4], uint32_t bf[][2]) {
        #pragma unroll
        for (int mi = 0; mi < 4; mi++) {
            uint32_t addr = a_s + sw_off(a_row_l + mi * 16, kk * 2 + a_chk_l);
            LDSM_X4(af[mi][0], af[mi][1], af[mi][2], af[mi][3], addr);
        }
        #pragma unroll
        for (int j2 = 0; j2 < 2; j2++) {
            uint32_t addr = b_s + sw_off(b_row_l + j2 * 16, kk * 2 + b_chk_l);
            uint32_t r0, r1, r2, r3;
            LDSM_X4(r0, r1, r2, r3, addr);
            bf[j2 * 2 + 0][0] = r0; bf[j2 * 2 + 0][1] = r1;
            bf[j2 * 2 + 1][0] = r2; bf[j2 * 2 + 1][1] = r3;
        }
    };

    // ========== phase 1: correction terms, f16 accumulation (2x rate) ==========
    uint32_t acc16[4][4][2];
    {
        const __half2 z = __halves2half2(__float2half(0.f), __float2half(0.f));
        uint32_t zu = *reinterpret_cast<const uint32_t*>(&z);
        #pragma unroll
        for (int i = 0; i < 4; i++)
            #pragma unroll
            for (int j = 0; j < 4; j++) {
                acc16[i][j][0] = zu;
                acc16[i][j][1] = zu;
            }
    }

    for (int i = 0; i < NCORR; i++) {
        CP_WAIT(STAGES - 2);
        __syncthreads();
        int j = i + STAGES - 1;
        if (j < NCHUNK) load_stage(j % STAGES, kc_of(j));
        CP_COMMIT();

        const uint32_t a_s = sb + (i % STAGES) * STAGE_BYTES;
        const uint32_t b_s = a_s + A_STAGE;
        #pragma unroll
        for (int kk = 0; kk < 4; kk++) {
            uint32_t af[4][4], bf[4][2];
            load_frags(a_s, b_s, kk, af, bf);
            #pragma unroll
            for (int mi = 0; mi < 4; mi++)
                #pragma unroll
                for (int nj = 0; nj < 4; nj++)
                    MMA16816_F16(acc16[mi][nj], af[mi], bf[nj]);
        }
        __syncthreads();
    }

    // convert f16 correction sums -> f32 accumulators
    float acc[4][4][4];
    #pragma unroll
    for (int mi = 0; mi < 4; mi++)
        #pragma unroll
        for (int nj = 0; nj < 4; nj++) {
            __half2 h0 = *reinterpret_cast<__half2*>(&acc16[mi][nj][0]);
            __half2 h1 = *reinterpret_cast<__half2*>(&acc16[mi][nj][1]);
            float2 f0 = __half22float2(h0);
            float2 f1 = __half22float2(h1);
            acc[mi][nj][0] = f0.x; acc[mi][nj][1] = f0.y;
            acc[mi][nj][2] = f1.x; acc[mi][nj][3] = f1.y;
        }

    // ========== phase 2: hi*hi term, f32 accumulation ==========
    for (int i = NCORR; i < NCHUNK; i++) {
        CP_WAIT(STAGES - 2);
        __syncthreads();
        int j = i + STAGES - 1;
        if (j < NCHUNK) load_stage(j % STAGES, kc_of(j));
        CP_COMMIT();

        const uint32_t a_s = sb + (i % STAGES) * STAGE_BYTES;
        const uint32_t b_s = a_s + A_STAGE;
        #pragma unroll
        for (int kk = 0; kk < 4; kk++) {
            uint32_t af[4][4], bf[4][2];
            load_frags(a_s, b_s, kk, af, bf);
            #pragma unroll
            for (int mi = 0; mi < 4; mi++)
                #pragma unroll
                for (int nj = 0; nj < 4; nj++)
                    MMA16816(acc[mi][nj], af[mi], bf[nj]);
        }
        __syncthreads();
    }

    // ---- epilogue: write fp32 accumulators ----
    const int er = lid >> 2;
    const int ec = (lid & 3) * 2;
    #pragma unroll
    for (int mi = 0; mi < 4; mi++) {
        int row = m0 + wm * 64 + mi * 16 + er;
        float* o0 = out + (size_t)row * NN + n0 + wn * 32 + ec;
        float* o1 = o0 + 8 * NN;
        #pragma unroll
        for (int nj = 0; nj < 4; nj++) {
            *reinterpret_cast<float2*>(o0 + nj * 8) =
                make_float2(acc[mi][nj][0], acc[mi][nj][1]);
            *reinterpret_cast<float2*>(o1 + nj * 8) =
                make_float2(acc[mi][nj][2], acc[mi][nj][3]);
        }
    }
}

// ===================== kernel 3: in-place row softmax =====================
__global__ void __launch_bounds__(256) softmax_kernel(float* __restrict__ out)
{
    __shared__ float smax[8];
    __shared__ float ssum[8];
    const int tid = threadIdx.x;
    float4* p = reinterpret_cast<float4*>(out + (size_t)blockIdx.x * NN);

    float4 v[8];
    #pragma unroll
    for (int j = 0; j < 8; j++) v[j] = p[tid + j * 256];

    float m = -1e30f;
    #pragma unroll
    for (int j = 0; j < 8; j++)
        m = fmaxf(m, fmaxf(fmaxf(v[j].x, v[j].y), fmaxf(v[j].z, v[j].w)));
    #pragma unroll
    for (int o = 16; o > 0; o >>= 1)
        m = fmaxf(m, __shfl_xor_sync(0xffffffffu, m, o));
    if ((tid & 31) == 0) smax[tid >> 5] = m;
    __syncthreads();
    m = smax[0];
    #pragma unroll
    for (int w = 1; w < 8; w++) m = fmaxf(m, smax[w]);

    float s = 0.f;
    #pragma unroll
    for (int j = 0; j < 8; j++) {
        v[j].x = __expf(v[j].x - m);
        v[j].y = __expf(v[j].y - m);
        v[j].z = __expf(v[j].z - m);
        v[j].w = __expf(v[j].w - m);
        s += v[j].x + v[j].y + v[j].z + v[j].w;
    }
    #pragma unroll
    for (int o = 16; o > 0; o >>= 1)
        s += __shfl_xor_sync(0xffffffffu, s, o);
    if ((tid & 31) == 0) ssum[tid >> 5] = s;
    __syncthreads();
    s = 0.f;
    #pragma unroll
    for (int w = 0; w < 8; w++) s += ssum[w];

    float inv = 1.0f / s;
    #pragma unroll
    for (int j = 0; j < 8; j++) {
        v[j].x *= inv; v[j].y *= inv; v[j].z *= inv; v[j].w *= inv;
        p[tid + j * 256] = v[j];
    }
}

// ===================== host launcher =====================
extern "C" void kernel_launch(void* const* d_in, const int* in_sizes, int n_in,
                              void* d_out, int out_size)
{
    const float* A = (const float*)d_in[0];   // out_state [8192, 1024]
    const float* B = (const float*)d_in[1];   // history   [8192, 1024]
    float* out = (float*)d_out;               // [8192, 8192] fp32

    void* pa = nullptr;
    void* pb = nullptr;
    cudaGetSymbolAddress(&pa, g_Ah);
    cudaGetSymbolAddress(&pb, g_Bh);

    // 1) split fp32 -> fp16 augmented operands
    convert_kernel<<<(MM * KK / 4) / 256, 256>>>(A, B, (__half*)pa, (__half*)pb);

    // 2) mma.sync GEMM -> energies into d_out
    static bool attr_set = false;
    if (!attr_set) {
        cudaFuncSetAttribute(gemm_kernel,
                             cudaFuncAttributeMaxDynamicSharedMemorySize, GEMM_SMEM);
        attr_set = true;
    }
    gemm_kernel<<<TILES_M * TILES_N, 256, GEMM_SMEM>>>(
        (const __half*)pa, (const __half*)pb, out);

    // 3) in-place row softmax
    softmax_kernel<<<MM, 256>>>(out);
}

// round 7
// speedup vs baseline: 1.0308x; 1.0308x over previous
#include <cuda_runtime.h>
#include <cuda_fp16.h>
#include <cstdint>
#include <cstddef>

// ===================== problem sizes =====================
static constexpr int MM   = 8192;   // state_len (rows)
static constexpr int NN   = 8192;   // seq_len   (cols, softmax axis)
static constexpr int KK   = 1024;   // hidden
static constexpr int KTOT = 3072;   // 3*KK : [hi*hi | lo*hi | hi*lo]

// ===================== GEMM config =====================
// CTA 128x128, 4 warps (2x2), warp tile 64x64, 3 stages, 96KB smem
// -> 2 CTAs/SM. LDSM traffic 192 B per MMA = 75% of smem crossbar
// (vs 100% with the 8-warp 64x32 layout) while tensor pipe stays at rt=8.
static constexpr int BM = 128, BN = 128, BK = 64;   // BK fp16 = 128B row
static constexpr int STAGES  = 3;
static constexpr int NCHUNK  = KTOT / BK;           // 48
static constexpr int TILES_M = MM / BM;             // 64
static constexpr int TILES_N = NN / BN;             // 64
static constexpr int A_STAGE = BM * BK * 2;         // 16384
static constexpr int B_STAGE = BN * BK * 2;         // 16384
static constexpr int STAGE_BYTES = A_STAGE + B_STAGE;          // 32768
static constexpr int GEMM_SMEM   = STAGES * STAGE_BYTES;       // 98304
static constexpr int GEMM_THREADS = 128;            // 4 warps

// ===================== scratch (allocation-free) =====================
__device__ __half g_Ah[(size_t)MM * KTOT];   // 48 MB
__device__ __half g_Bh[(size_t)NN * KTOT];   // 48 MB

// ===================== PTX helpers (base sm_100-safe) =====================
__device__ __forceinline__ uint32_t smem_to_u32(const void* p) {
    uint32_t a;
    asm("{ .reg .u64 t; cvta.to.shared.u64 t, %1; cvt.u32.u64 %0, t; }"
        : "=r"(a) : "l"(p));
    return a;
}

#define CP_ASYNC_16(dst, src) \
    asm volatile("cp.async.cg.shared.global [%0], [%1], 16;" \
                 :: "r"(dst), "l"(src) : "memory")
#define CP_COMMIT() \
    asm volatile("cp.async.commit_group;" ::: "memory")
#define CP_WAIT(n) \
    asm volatile("cp.async.wait_group %0;" :: "n"(n) : "memory")

#define LDSM_X4(r0, r1, r2, r3, addr) \
    asm volatile("ldmatrix.sync.aligned.m8n8.x4.shared.b16 {%0,%1,%2,%3}, [%4];" \
                 : "=r"(r0), "=r"(r1), "=r"(r2), "=r"(r3) : "r"(addr))

#define MMA16816(d, a, b) \
    asm volatile("mma.sync.aligned.m16n8k16.row.col.f32.f16.f16.f32 " \
                 "{%0,%1,%2,%3}, {%4,%5,%6,%7}, {%8,%9}, {%0,%1,%2,%3};" \
                 : "+f"((d)[0]), "+f"((d)[1]), "+f"((d)[2]), "+f"((d)[3]) \
                 : "r"((a)[0]), "r"((a)[1]), "r"((a)[2]), "r"((a)[3]), \
                   "r"((b)[0]), "r"((b)[1]))

// SW128-style XOR swizzle: 128B rows, 8 x 16B chunks; chunk' = chunk ^ (row & 7)
__device__ __forceinline__ uint32_t sw_off(int row, int chunk) {
    return (uint32_t)(row * 128 + (((chunk) ^ (row & 7)) << 4));
}

// ===================== kernel 1: fp32 -> fp16 3-way split =====================
__device__ __forceinline__ void split2(float x, __half& h, __half& l) {
    h = __float2half_rn(x);
    l = __float2half_rn(x - __half2float(h));
}
__device__ __forceinline__ void st4h(__half* p, __half a, __half b, __half c, __half d) {
    __half2 lo = __halves2half2(a, b);
    __half2 hi = __halves2half2(c, d);
    uint2 u;
    u.x = *reinterpret_cast<uint32_t*>(&lo);
    u.y = *reinterpret_cast<uint32_t*>(&hi);
    *reinterpret_cast<uint2*>(p) = u;
}

__global__ void __launch_bounds__(256) convert_kernel(
    const float* __restrict__ A, const float* __restrict__ B,
    __half* __restrict__ Ah, __half* __restrict__ Bh)
{
    int idx = blockIdx.x * 256 + threadIdx.x;   // float4 index
    int i  = idx >> 8;                          // row (KK/4 = 256 float4 per row)
    int k4 = idx & 255;
    size_t base = (size_t)i * KTOT + (size_t)k4 * 4;

    float4 a = reinterpret_cast<const float4*>(A)[idx];
    float4 b = reinterpret_cast<const float4*>(B)[idx];

    __half ah0, al0, ah1, al1, ah2, al2, ah3, al3;
    split2(a.x, ah0, al0); split2(a.y, ah1, al1);
    split2(a.z, ah2, al2); split2(a.w, ah3, al3);
    st4h(Ah + base,          ah0, ah1, ah2, ah3);   // hi
    st4h(Ah + base + KK,     al0, al1, al2, al3);   // lo
    st4h(Ah + base + 2 * KK, ah0, ah1, ah2, ah3);   // hi

    __half bh0, bl0, bh1, bl1, bh2, bl2, bh3, bl3;
    split2(b.x, bh0, bl0); split2(b.y, bh1, bl1);
    split2(b.z, bh2, bl2); split2(b.w, bh3, bl3);
    st4h(Bh + base,          bh0, bh1, bh2, bh3);   // hi
    st4h(Bh + base + KK,     bh0, bh1, bh2, bh3);   // hi
    st4h(Bh + base + 2 * KK, bl0, bl1, bl2, bl3);   // lo
}

// ===================== kernel 2: mma.sync fp16 GEMM =====================
// out[m, n] = sum_k A'[m,k] * B'[n,k]   (fp32)
// CTA tile 128x128, 4 warps (2M x 2N), warp tile 64x64. 2 CTAs/SM.
__global__ void __launch_bounds__(GEMM_THREADS, 2)
gemm_kernel(const __half* __restrict__ Ah, const __half* __restrict__ Bh,
            float* __restrict__ out)
{
    extern __shared__ __align__(1024) char smem[];
    const uint32_t sb = smem_to_u32(smem);
    const int tid = threadIdx.x;
    const int wid = tid >> 5;
    const int lid = tid & 31;

    // supertile swizzle for L2 reuse: 8x8 groups
    constexpr int PER_G = 64;
    constexpr int GROUPS_N = TILES_N / 8;   // 8
    int id = blockIdx.x;
    int g = id / PER_G, r = id % PER_G;
    int tm = (g / GROUPS_N) * 8 + r / 8;
    int tn = (g % GROUPS_N) * 8 + r % 8;
    const int m0 = tm * BM, n0 = tn * BN;

    // warp layout: 2 (M) x 2 (N); warp tile 64 x 64
    const int wm = wid & 1;        // 0..1
    const int wn = wid >> 1;       // 0..1

    // cp.async assignment: 16B chunks; 128 threads cover 16 rows per pass
    const int lr = tid >> 3;       // base row (0..15)
    const int lc = tid & 7;        // chunk 0..7

    const __half* gA = Ah + (size_t)(m0 + lr) * KTOT + lc * 8;
    const __half* gB = Bh + (size_t)(n0 + lr) * KTOT + lc * 8;

    // accumulators: 4 m-tiles x 8 n-tiles x 4 floats = 128 regs
    float acc[4][8][4];
    #pragma unroll
    for (int i = 0; i < 4; i++)
        #pragma unroll
        for (int j = 0; j < 8; j++)
            #pragma unroll
            for (int q = 0; q < 4; q++) acc[i][j][q] = 0.f;

    // ---- load one stage of A+B via cp.async (8 A rows + 8 B rows per thread) ----
    auto load_stage = [&](int s, int kc) {
        uint32_t a_s = sb + s * STAGE_BYTES;
        uint32_t b_s = a_s + A_STAGE;
        const __half* ga = gA + (size_t)kc * BK;
        const __half* gb = gB + (size_t)kc * BK;
        #pragma unroll
        for (int i = 0; i < 8; i++) {
            CP_ASYNC_16(a_s + sw_off(lr + i * 16, lc), ga + (size_t)i * 16 * KTOT);
            CP_ASYNC_16(b_s + sw_off(lr + i * 16, lc), gb + (size_t)i * 16 * KTOT);
        }
    };

    // prologue: fill STAGES-1 stages
    #pragma unroll
    for (int s = 0; s < STAGES - 1; s++) {
        load_stage(s, s);
        CP_COMMIT();
    }

    // ldmatrix lane addressing (within a stage)
    const int a_row_l = wm * 64 + (lid & 15);
    const int a_chk_l = (lid >> 4);
    const int b_row_l = wn * 64 + (lid & 7) + ((lid >> 4) & 1) * 8;
    const int b_chk_l = (lid >> 3) & 1;

    auto load_af = [&](uint32_t a_s, int kk, uint32_t af[][4]) {
        #pragma unroll
        for (int mi = 0; mi < 4; mi++) {
            uint32_t addr = a_s + sw_off(a_row_l + mi * 16, kk * 2 + a_chk_l);
            LDSM_X4(af[mi][0], af[mi][1], af[mi][2], af[mi][3], addr);
        }
    };
    auto load_bf = [&](uint32_t b_s, int kk, uint32_t bf[][2]) {
        #pragma unroll
        for (int j2 = 0; j2 < 4; j2++) {
            uint32_t addr = b_s + sw_off(b_row_l + j2 * 16, kk * 2 + b_chk_l);
            uint32_t r0, r1, r2, r3;
            LDSM_X4(r0, r1, r2, r3, addr);
            bf[j2 * 2 + 0][0] = r0; bf[j2 * 2 + 0][1] = r1;
            bf[j2 * 2 + 1][0] = r2; bf[j2 * 2 + 1][1] = r3;
        }
    };

    for (int i = 0; i < NCHUNK; i++) {
        CP_WAIT(STAGES - 2);
        __syncthreads();

        // refill the slot consumed at iter i-1
        int j = i + STAGES - 1;
        if (j < NCHUNK) load_stage(j % STAGES, j);
        CP_COMMIT();

        const uint32_t a_s = sb + (i % STAGES) * STAGE_BYTES;
        const uint32_t b_s = a_s + A_STAGE;

        // software-pipelined fragments: LDSM for kk+1 overlaps MMA for kk
        uint32_t af[2][4][4];
        uint32_t bf[2][8][2];
        load_af(a_s, 0, af[0]);
        load_bf(b_s, 0, bf[0]);
        #pragma unroll
        for (int kk = 0; kk < 4; kk++) {
            int cur = kk & 1, nxt = cur ^ 1;
            if (kk < 3) {
                load_af(a_s, kk + 1, af[nxt]);
                load_bf(b_s, kk + 1, bf[nxt]);
            }
            #pragma unroll
            for (int mi = 0; mi < 4; mi++)
                #pragma unroll
                for (int nj = 0; nj < 8; nj++)
                    MMA16816(acc[mi][nj], af[cur][mi], bf[cur][nj]);
        }
        __syncthreads();
    }

    // ---- epilogue: write fp32 accumulators ----
    const int er = lid >> 2;
    const int ec = (lid & 3) * 2;
    #pragma unroll
    for (int mi = 0; mi < 4; mi++) {
        int row = m0 + wm * 64 + mi * 16 + er;
        float* o0 = out + (size_t)row * NN + n0 + wn * 64 + ec;
        float* o1 = o0 + 8 * NN;
        #pragma unroll
        for (int nj = 0; nj < 8; nj++) {
            *reinterpret_cast<float2*>(o0 + nj * 8) =
                make_float2(acc[mi][nj][0], acc[mi][nj][1]);
            *reinterpret_cast<float2*>(o1 + nj * 8) =
                make_float2(acc[mi][nj][2], acc[mi][nj][3]);
        }
    }
}

// ===================== kernel 3: in-place row softmax =====================
__global__ void __launch_bounds__(256) softmax_kernel(float* __restrict__ out)
{
    __shared__ float smax[8];
    __shared__ float ssum[8];
    const int tid = threadIdx.x;
    float4* p = reinterpret_cast<float4*>(out + (size_t)blockIdx.x * NN);

    float4 v[8];
    #pragma unroll
    for (int j = 0; j < 8; j++) v[j] = p[tid + j * 256];

    float m = -1e30f;
    #pragma unroll
    for (int j = 0; j < 8; j++)
        m = fmaxf(m, fmaxf(fmaxf(v[j].x, v[j].y), fmaxf(v[j].z, v[j].w)));
    #pragma unroll
    for (int o = 16; o > 0; o >>= 1)
        m = fmaxf(m, __shfl_xor_sync(0xffffffffu, m, o));
    if ((tid & 31) == 0) smax[tid >> 5] = m;
    __syncthreads();
    m = smax[0];
    #pragma unroll
    for (int w = 1; w < 8; w++) m = fmaxf(m, smax[w]);

    float s = 0.f;
    #pragma unroll
    for (int j = 0; j < 8; j++) {
        v[j].x = __expf(v[j].x - m);
        v[j].y = __expf(v[j].y - m);
        v[j].z = __expf(v[j].z - m);
        v[j].w = __expf(v[j].w - m);
        s += v[j].x + v[j].y + v[j].z + v[j].w;
    }
    #pragma unroll
    for (int o = 16; o > 0; o >>= 1)
        s += __shfl_xor_sync(0xffffffffu, s, o);
    if ((tid & 31) == 0) ssum[tid >> 5] = s;
    __syncthreads();
    s = 0.f;
    #pragma unroll
    for (int w = 0; w < 8; w++) s += ssum[w];

    float inv = 1.0f / s;
    #pragma unroll
    for (int j = 0; j < 8; j++) {
        v[j].x *= inv; v[j].y *= inv; v[j].z *= inv; v[j].w *= inv;
        p[tid + j * 256] = v[j];
    }
}

// ===================== host launcher =====================
extern "C" void kernel_launch(void* const* d_in, const int* in_sizes, int n_in,
                              void* d_out, int out_size)
{
    const float* A = (const float*)d_in[0];   // out_state [8192, 1024]
    const float* B = (const float*)d_in[1];   // history   [8192, 1024]
    float* out = (float*)d_out;               // [8192, 8192] fp32

    void* pa = nullptr;
    void* pb = nullptr;
    cudaGetSymbolAddress(&pa, g_Ah);
    cudaGetSymbolAddress(&pb, g_Bh);

    // 1) split fp32 -> fp16 augmented operands
    convert_kernel<<<(MM * KK / 4) / 256, 256>>>(A, B, (__half*)pa, (__half*)pb);

    // 2) mma.sync GEMM -> energies into d_out
    static bool attr_set = false;
    if (!attr_set) {
        cudaFuncSetAttribute(gemm_kernel,
                             cudaFuncAttributeMaxDynamicSharedMemorySize, GEMM_SMEM);
        attr_set = true;
    }
    gemm_kernel<<<TILES_M * TILES_N, GEMM_THREADS, GEMM_SMEM>>>(
        (const __half*)pa, (const __half*)pb, out);

    // 3) in-place row softmax
    softmax_kernel<<<MM, 256>>>(out);
}

// round 8
// speedup vs baseline: 1.0387x; 1.0076x over previous
#include <cuda_runtime.h>
#include <cuda_fp16.h>
#include <cstdint>
#include <cstddef>

// ===================== problem sizes =====================
static constexpr int MM   = 8192;   // state_len (rows)
static constexpr int NN   = 8192;   // seq_len   (cols, softmax axis)
static constexpr int KK   = 1024;   // hidden
static constexpr int KTOT = 3072;   // 3*KK : [hi*hi | lo*hi | hi*lo]

// ===================== GEMM config =====================
// CTA 128x128, 4 warps (2x2), warp tile 64x64, 3 stages, 96KB smem
// -> 2 CTAs/SM. Single __syncthreads per K-chunk (the trailing one is
// redundant: next iteration's CP_WAIT+sync already orders slot reuse).
static constexpr int BM = 128, BN = 128, BK = 64;   // BK fp16 = 128B row
static constexpr int STAGES  = 3;
static constexpr int NCHUNK  = KTOT / BK;           // 48
static constexpr int TILES_M = MM / BM;             // 64
static constexpr int TILES_N = NN / BN;             // 64
static constexpr int A_STAGE = BM * BK * 2;         // 16384
static constexpr int B_STAGE = BN * BK * 2;         // 16384
static constexpr int STAGE_BYTES = A_STAGE + B_STAGE;          // 32768
static constexpr int GEMM_SMEM   = STAGES * STAGE_BYTES;       // 98304
static constexpr int GEMM_THREADS = 128;            // 4 warps

// ===================== scratch (allocation-free) =====================
__device__ __half g_Ah[(size_t)MM * KTOT];   // 48 MB
__device__ __half g_Bh[(size_t)NN * KTOT];   // 48 MB

// ===================== PTX helpers (base sm_100-safe) =====================
__device__ __forceinline__ uint32_t smem_to_u32(const void* p) {
    uint32_t a;
    asm("{ .reg .u64 t; cvta.to.shared.u64 t, %1; cvt.u32.u64 %0, t; }"
        : "=r"(a) : "l"(p));
    return a;
}

#define CP_ASYNC_16(dst, src) \
    asm volatile("cp.async.cg.shared.global [%0], [%1], 16;" \
                 :: "r"(dst), "l"(src) : "memory")
#define CP_COMMIT() \
    asm volatile("cp.async.commit_group;" ::: "memory")
#define CP_WAIT(n) \
    asm volatile("cp.async.wait_group %0;" :: "n"(n) : "memory")

#define LDSM_X4(r0, r1, r2, r3, addr) \
    asm volatile("ldmatrix.sync.aligned.m8n8.x4.shared.b16 {%0,%1,%2,%3}, [%4];" \
                 : "=r"(r0), "=r"(r1), "=r"(r2), "=r"(r3) : "r"(addr))

#define MMA16816(d, a, b) \
    asm volatile("mma.sync.aligned.m16n8k16.row.col.f32.f16.f16.f32 " \
                 "{%0,%1,%2,%3}, {%4,%5,%6,%7}, {%8,%9}, {%0,%1,%2,%3};" \
                 : "+f"((d)[0]), "+f"((d)[1]), "+f"((d)[2]), "+f"((d)[3]) \
                 : "r"((a)[0]), "r"((a)[1]), "r"((a)[2]), "r"((a)[3]), \
                   "r"((b)[0]), "r"((b)[1]))

// SW128-style XOR swizzle: 128B rows, 8 x 16B chunks; chunk' = chunk ^ (row & 7)
__device__ __forceinline__ uint32_t sw_off(int row, int chunk) {
    return (uint32_t)(row * 128 + (((chunk) ^ (row & 7)) << 4));
}

// ===================== kernel 1: fp32 -> fp16 3-way split =====================
__device__ __forceinline__ void split2(float x, __half& h, __half& l) {
    h = __float2half_rn(x);
    l = __float2half_rn(x - __half2float(h));
}
__device__ __forceinline__ void st4h(__half* p, __half a, __half b, __half c, __half d) {
    __half2 lo = __halves2half2(a, b);
    __half2 hi = __halves2half2(c, d);
    uint2 u;
    u.x = *reinterpret_cast<uint32_t*>(&lo);
    u.y = *reinterpret_cast<uint32_t*>(&hi);
    *reinterpret_cast<uint2*>(p) = u;
}

__global__ void __launch_bounds__(256) convert_kernel(
    const float* __restrict__ A, const float* __restrict__ B,
    __half* __restrict__ Ah, __half* __restrict__ Bh)
{
    int idx = blockIdx.x * 256 + threadIdx.x;   // float4 index
    int i  = idx >> 8;                          // row (KK/4 = 256 float4 per row)
    int k4 = idx & 255;
    size_t base = (size_t)i * KTOT + (size_t)k4 * 4;

    float4 a = reinterpret_cast<const float4*>(A)[idx];
    float4 b = reinterpret_cast<const float4*>(B)[idx];

    __half ah0, al0, ah1, al1, ah2, al2, ah3, al3;
    split2(a.x, ah0, al0); split2(a.y, ah1, al1);
    split2(a.z, ah2, al2); split2(a.w, ah3, al3);
    st4h(Ah + base,          ah0, ah1, ah2, ah3);   // hi
    st4h(Ah + base + KK,     al0, al1, al2, al3);   // lo
    st4h(Ah + base + 2 * KK, ah0, ah1, ah2, ah3);   // hi

    __half bh0, bl0, bh1, bl1, bh2, bl2, bh3, bl3;
    split2(b.x, bh0, bl0); split2(b.y, bh1, bl1);
    split2(b.z, bh2, bl2); split2(b.w, bh3, bl3);
    st4h(Bh + base,          bh0, bh1, bh2, bh3);   // hi
    st4h(Bh + base + KK,     bh0, bh1, bh2, bh3);   // hi
    st4h(Bh + base + 2 * KK, bl0, bl1, bl2, bl3);   // lo
}

// ===================== kernel 2: mma.sync fp16 GEMM =====================
// out[m, n] = sum_k A'[m,k] * B'[n,k]   (fp32)
// CTA tile 128x128, 4 warps (2M x 2N), warp tile 64x64. 2 CTAs/SM.
__global__ void __launch_bounds__(GEMM_THREADS, 2)
gemm_kernel(const __half* __restrict__ Ah, const __half* __restrict__ Bh,
            float* __restrict__ out)
{
    extern __shared__ __align__(1024) char smem[];
    const uint32_t sb = smem_to_u32(smem);
    const int tid = threadIdx.x;
    const int wid = tid >> 5;
    const int lid = tid & 31;

    // supertile swizzle for L2 reuse: 8x8 groups
    constexpr int PER_G = 64;
    constexpr int GROUPS_N = TILES_N / 8;   // 8
    int id = blockIdx.x;
    int g = id / PER_G, r = id % PER_G;
    int tm = (g / GROUPS_N) * 8 + r / 8;
    int tn = (g % GROUPS_N) * 8 + r % 8;
    const int m0 = tm * BM, n0 = tn * BN;

    // warp layout: 2 (M) x 2 (N); warp tile 64 x 64
    const int wm = wid & 1;        // 0..1
    const int wn = wid >> 1;       // 0..1

    // cp.async assignment: 16B chunks; 128 threads cover 16 rows per pass
    const int lr = tid >> 3;       // base row (0..15)
    const int lc = tid & 7;        // chunk 0..7

    const __half* gA = Ah + (size_t)(m0 + lr) * KTOT + lc * 8;
    const __half* gB = Bh + (size_t)(n0 + lr) * KTOT + lc * 8;

    // accumulators: 4 m-tiles x 8 n-tiles x 4 floats = 128 regs
    float acc[4][8][4];
    #pragma unroll
    for (int i = 0; i < 4; i++)
        #pragma unroll
        for (int j = 0; j < 8; j++)
            #pragma unroll
            for (int q = 0; q < 4; q++) acc[i][j][q] = 0.f;

    // ---- load one stage of A+B via cp.async (8 A rows + 8 B rows per thread) ----
    auto load_stage = [&](int s, int kc) {
        uint32_t a_s = sb + s * STAGE_BYTES;
        uint32_t b_s = a_s + A_STAGE;
        const __half* ga = gA + (size_t)kc * BK;
        const __half* gb = gB + (size_t)kc * BK;
        #pragma unroll
        for (int i = 0; i < 8; i++) {
            CP_ASYNC_16(a_s + sw_off(lr + i * 16, lc), ga + (size_t)i * 16 * KTOT);
            CP_ASYNC_16(b_s + sw_off(lr + i * 16, lc), gb + (size_t)i * 16 * KTOT);
        }
    };

    // prologue: fill STAGES-1 stages
    #pragma unroll
    for (int s = 0; s < STAGES - 1; s++) {
        load_stage(s, s);
        CP_COMMIT();
    }

    // ldmatrix lane addressing (within a stage)
    const int a_row_l = wm * 64 + (lid & 15);
    const int a_chk_l = (lid >> 4);
    const int b_row_l = wn * 64 + (lid & 7) + ((lid >> 4) & 1) * 8;
    const int b_chk_l = (lid >> 3) & 1;

    auto load_af = [&](uint32_t a_s, int kk, uint32_t af[][4]) {
        #pragma unroll
        for (int mi = 0; mi < 4; mi++) {
            uint32_t addr = a_s + sw_off(a_row_l + mi * 16, kk * 2 + a_chk_l);
            LDSM_X4(af[mi][0], af[mi][1], af[mi][2], af[mi][3], addr);
        }
    };
    auto load_bf = [&](uint32_t b_s, int kk, uint32_t bf[][2]) {
        #pragma unroll
        for (int j2 = 0; j2 < 4; j2++) {
            uint32_t addr = b_s + sw_off(b_row_l + j2 * 16, kk * 2 + b_chk_l);
            uint32_t r0, r1, r2, r3;
            LDSM_X4(r0, r1, r2, r3, addr);
            bf[j2 * 2 + 0][0] = r0; bf[j2 * 2 + 0][1] = r1;
            bf[j2 * 2 + 1][0] = r2; bf[j2 * 2 + 1][1] = r3;
        }
    };

    for (int i = 0; i < NCHUNK; i++) {
        // stage i arrived (my groups), then CTA-wide publish + slot-reuse fence.
        // Order matters: CP_WAIT must precede the barrier so every thread's
        // cp.async data for stage i is visible to every other thread's LDSM.
        CP_WAIT(STAGES - 2);
        __syncthreads();

        // refill the slot consumed at iter i-1 (ordered after the sync above)
        int j = i + STAGES - 1;
        if (j < NCHUNK) load_stage(j % STAGES, j);
        CP_COMMIT();

        const uint32_t a_s = sb + (i % STAGES) * STAGE_BYTES;
        const uint32_t b_s = a_s + A_STAGE;

        // software-pipelined fragments: LDSM for kk+1 overlaps MMA for kk
        uint32_t af[2][4][4];
        uint32_t bf[2][8][2];
        load_af(a_s, 0, af[0]);
        load_bf(b_s, 0, bf[0]);
        #pragma unroll
        for (int kk = 0; kk < 4; kk++) {
            int cur = kk & 1, nxt = cur ^ 1;
            if (kk < 3) {
                load_af(a_s, kk + 1, af[nxt]);
                load_bf(b_s, kk + 1, bf[nxt]);
            }
            #pragma unroll
            for (int mi = 0; mi < 4; mi++)
                #pragma unroll
                for (int nj = 0; nj < 8; nj++)
                    MMA16816(acc[mi][nj], af[cur][mi], bf[cur][nj]);
        }
        // NOTE: no trailing __syncthreads — the next iteration's
        // CP_WAIT + __syncthreads already orders all reads of this slot
        // before its refill (load_stage is issued after that sync).
    }

    // ---- epilogue: write fp32 accumulators ----
    const int er = lid >> 2;
    const int ec = (lid & 3) * 2;
    #pragma unroll
    for (int mi = 0; mi < 4; mi++) {
        int row = m0 + wm * 64 + mi * 16 + er;
        float* o0 = out + (size_t)row * NN + n0 + wn * 64 + ec;
        float* o1 = o0 + 8 * NN;
        #pragma unroll
        for (int nj = 0; nj < 8; nj++) {
            *reinterpret_cast<float2*>(o0 + nj * 8) =
                make_float2(acc[mi][nj][0], acc[mi][nj][1]);
            *reinterpret_cast<float2*>(o1 + nj * 8) =
                make_float2(acc[mi][nj][2], acc[mi][nj][3]);
        }
    }
}

// ===================== kernel 3: in-place row softmax =====================
__global__ void __launch_bounds__(256) softmax_kernel(float* __restrict__ out)
{
    __shared__ float smax[8];
    __shared__ float ssum[8];
    const int tid = threadIdx.x;
    float4* p = reinterpret_cast<float4*>(out + (size_t)blockIdx.x * NN);

    float4 v[8];
    #pragma unroll
    for (int j = 0; j < 8; j++) v[j] = p[tid + j * 256];

    float m = -1e30f;
    #pragma unroll
    for (int j = 0; j < 8; j++)
        m = fmaxf(m, fmaxf(fmaxf(v[j].x, v[j].y), fmaxf(v[j].z, v[j].w)));
    #pragma unroll
    for (int o = 16; o > 0; o >>= 1)
        m = fmaxf(m, __shfl_xor_sync(0xffffffffu, m, o));
    if ((tid & 31) == 0) smax[tid >> 5] = m;
    __syncthreads();
    m = smax[0];
    #pragma unroll
    for (int w = 1; w < 8; w++) m = fmaxf(m, smax[w]);

    float s = 0.f;
    #pragma unroll
    for (int j = 0; j < 8; j++) {
        v[j].x = __expf(v[j].x - m);
        v[j].y = __expf(v[j].y - m);
        v[j].z = __expf(v[j].z - m);
        v[j].w = __expf(v[j].w - m);
        s += v[j].x + v[j].y + v[j].z + v[j].w;
    }
    #pragma unroll
    for (int o = 16; o > 0; o >>= 1)
        s += __shfl_xor_sync(0xffffffffu, s, o);
    if ((tid & 31) == 0) ssum[tid >> 5] = s;
    __syncthreads();
    s = 0.f;
    #pragma unroll
    for (int w = 0; w < 8; w++) s += ssum[w];

    float inv = 1.0f / s;
    #pragma unroll
    for (int j = 0; j < 8; j++) {
        v[j].x *= inv; v[j].y *= inv; v[j].z *= inv; v[j].w *= inv;
        p[tid + j * 256] = v[j];
    }
}

// ===================== host launcher =====================
extern "C" void kernel_launch(void* const* d_in, const int* in_sizes, int n_in,
                              void* d_out, int out_size)
{
    const float* A = (const float*)d_in[0];   // out_state [8192, 1024]
    const float* B = (const float*)d_in[1];   // history   [8192, 1024]
    float* out = (float*)d_out;               // [8192, 8192] fp32

    void* pa = nullptr;
    void* pb = nullptr;
    cudaGetSymbolAddress(&pa, g_Ah);
    cudaGetSymbolAddress(&pb, g_Bh);

    // 1) split fp32 -> fp16 augmented operands
    convert_kernel<<<(MM * KK / 4) / 256, 256>>>(A, B, (__half*)pa, (__half*)pb);

    // 2) mma.sync GEMM -> energies into d_out
    static bool attr_set = false;
    if (!attr_set) {
        cudaFuncSetAttribute(gemm_kernel,
                             cudaFuncAttributeMaxDynamicSharedMemorySize, GEMM_SMEM);
        attr_set = true;
    }
    gemm_kernel<<<TILES_M * TILES_N, GEMM_THREADS, GEMM_SMEM>>>(
        (const __half*)pa, (const __half*)pb, out);

    // 3) in-place row softmax
    softmax_kernel<<<MM, 256>>>(out);
}